// round 12
// baseline (speedup 1.0000x reference)
#include <cuda_runtime.h>
#include <math.h>

#define NPTS    200000
#define NBINS   512
#define TPB     256
#define BLOCKS  888                        // 6 blocks/SM x 148 SMs, uniform wave
#define PPB     226                        // points per block (888*226 >= NPTS)
#define NSLOT   16                         // 16 aligned 32-bin slots
#define NCOPY   32                         // global hist copies

// Global accumulators + completion ticket. Invariant: all zero at launch
// start; the last block restores them after writing d_out (graph-replay safe).
__device__ float        g_hist[NCOPY][NBINS];
__device__ unsigned int g_ticket;

__device__ __forceinline__ float ex2f(float x) {
    float y;
    asm("ex2.approx.f32 %0, %1;" : "=f"(y) : "f"(x));
    return y;
}
__device__ __forceinline__ float ldcg(const float* p) {
    float v;
    asm volatile("ld.global.cg.f32 %0, [%1];" : "=f"(v) : "l"(p));
    return v;
}

// ---------------------------------------------------------------------------
// Single fused kernel, register-accumulator design:
//  - fold: each thread folds one point, pushes tid onto the list of every
//    32-bin slot its window [b0,b1] overlaps (b1 capped at 511 -> no pad work)
//  - scatter: warp w owns slots {w, 15-w} (density-balanced pairing); for each
//    listed point it evaluates the slot's 32 bins and accumulates in a
//    REGISTER. No shared hist, no zero/merge phases, no LDS-RMW chain.
//  - left clip exact via saturate; right edge 4 sigma (rel_err ~1.7e-4).
// ---------------------------------------------------------------------------
__global__ void __launch_bounds__(TPB, 6) main_kernel(
        const float* __restrict__ means,
        const float* __restrict__ scan_point,
        const float* __restrict__ colours,
        const float* __restrict__ coefficients,
        const float* __restrict__ opacities,
        const float* __restrict__ scales,
        float* __restrict__ out)
{
    __shared__ float4        cp[TPB];            // 4 KB: (k, mneg, B, A2)
    __shared__ float         cI[TPB];            // 1 KB: intensity
    __shared__ unsigned char s_list[NSLOT][TPB]; // 4 KB: slot -> point tids
    __shared__ int           s_cnt[NSLOT];
    __shared__ unsigned int  s_last;

    const int tid  = threadIdx.x;
    const int w    = tid >> 5;
    const int lane = tid & 31;

    if (tid < NSLOT) s_cnt[tid] = 0;
    __syncthreads();

    // ---- fold phase: one point per thread ----
    const int p = blockIdx.x * PPB + tid;
    float4 P = make_float4(0.f, 0.f, 0.f, 0.f);
    float  I = 0.f;
    if (tid < PPB && p < NPTS) {
        float sx = scan_point[0], sy = scan_point[1], sz = scan_point[2];
        float dx = means[3 * p + 0] - sx;
        float dy = means[3 * p + 1] - sy;
        float dz = means[3 * p + 2] - sz;
        float r0 = sqrtf(fmaf(dx, dx, fmaf(dy, dy, dz * dz)));

        float sigma = fmaxf(__expf(scales[p]), 0.005f);   // BIN_RES/2
        float sinv  = __frcp_rn(sigma);

        float coeff = __frcp_rn(1.0f + __expf(-coefficients[p]));

        float op = opacities[p];
        float co = colours[p];
        I = (op * op) * (co * co);

        // pdf*(h/2) = e * (A + B*(r-r0));  gg = fma(r, B, A2)
        float A  = 0.005f * 0.3989422804014327f * coeff * sinv;
        float B  = 0.005f * (1.0f - coeff) * sinv * sinv;
        float A2 = A - B * r0;

        // e = 2^(-(d*k)^2), k = sinv*sqrt(0.5*log2 e)
        float k    = 0.84932180028802f * sinv;
        float mneg = -r0 * k;
        P = make_float4(k, mneg, B, A2);

        // window: left = clip zero-crossing r0 - A/B (exact), right = 4 sigma
        float W   = 3.39729f / k;             // 4 sigma in r units
        float AoB = A * __frcp_rn(B);         // ~0.4 sigma
        float lo  = r0 - fminf(W, AoB);
        float hi  = r0 + W;
        int b0 = max(0,   (int)ceilf (lo * 200.0f - 1.0f));
        int b1 = min(511, (int)floorf(hi * 200.0f - 1.0f));
        if (b1 >= b0) {
            int s0 = b0 >> 5, s1 = b1 >> 5;
            for (int s = s0; s <= s1; ++s) {
                int i = atomicAdd(&s_cnt[s], 1);
                s_list[s][i] = (unsigned char)tid;
            }
        }
    }
    cp[tid] = P;
    cI[tid] = I;
    __syncthreads();

    // ---- scatter: warp w -> slots {w, 15-w}; register accumulation ----
    float* __restrict__ gh = g_hist[blockIdx.x & (NCOPY - 1)];
    #pragma unroll
    for (int ss = 0; ss < 2; ++ss) {
        const int   s   = ss ? (NSLOT - 1 - w) : w;
        const int   n   = s_cnt[s];
        const float rt  = 0.005f * (float)(s * 32 + lane + 1);
        float acc = 0.0f;
        #pragma unroll 2
        for (int e = 0; e < n; ++e) {
            int    pos = s_list[s][e];
            float4 q   = cp[pos];
            float  u   = fmaf(rt, q.x, q.y);   // (r - r0) * k
            float  e2  = ex2f(u * -u);         // exp(-0.5 (d/sig)^2)
            float  gg  = fmaf(rt, q.z, q.w);   // A + B*(r - r0)
            float  pr  = __saturatef(e2 * gg); // clip (left clip exact here)
            acc = fmaf(cI[pos], pr, acc);
        }
        atomicAdd(&gh[s * 32 + lane], acc);    // coalesced RED, 32-way copies
    }

    // ---- last-block finalize (no spinning: only the final arrival acts) ----
    __threadfence();
    if (tid == 0)
        s_last = atomicAdd(&g_ticket, 1u);
    __syncthreads();

    if (s_last == BLOCKS - 1) {
        __threadfence();
        #pragma unroll
        for (int b = tid; b < NBINS; b += TPB) {
            float v = 0.0f;
            #pragma unroll
            for (int c = 0; c < NCOPY; ++c) {
                v += ldcg(&g_hist[c][b]);
                g_hist[c][b] = 0.0f;              // restore invariant
            }
            float r = 0.005f * (float)(b + 1);
            out[b] = v / (r * r);
        }
        __threadfence();
        __syncthreads();
        if (tid == 0) g_ticket = 0u;              // restore invariant
    }
}

// ---------------------------------------------------------------------------
extern "C" void kernel_launch(void* const* d_in, const int* in_sizes, int n_in,
                              void* d_out, int out_size)
{
    const float* means        = (const float*)d_in[0];
    const float* scan_point   = (const float*)d_in[1];
    const float* colours      = (const float*)d_in[2];
    const float* coefficients = (const float*)d_in[3];
    const float* opacities    = (const float*)d_in[4];
    const float* scales       = (const float*)d_in[5];

    float* out = (float*)d_out;

    main_kernel<<<BLOCKS, TPB>>>(means, scan_point, colours,
                                 coefficients, opacities, scales, out);
}